// round 5
// baseline (speedup 1.0000x reference)
#include <cuda_runtime.h>
#include <cuda_bf16.h>
#include <math.h>

// GPT-2 small, 4 layers: B=2, S=1024, E=768, H=12, D=64, V=50257
#define B_   2
#define S_   1024
#define E_   768
#define H_   12
#define D_   64
#define L_   4
#define V_   50257
#define VP_  50304          // V padded to multiple of 128
#define M_   (B_ * S_)      // 2048
#define E3_  (3 * E_)       // 2304
#define E4_  (4 * E_)       // 3072
#define BH_  (B_ * H_)      // 24

// ---------------- scratch (allocation-free: device globals) ----------------
__device__ float g_x[M_ * E_];
__device__ float g_h[M_ * E_];
__device__ float g_qkv[M_ * E3_];
__device__ float g_scores[(size_t)BH_ * S_ * S_];
__device__ float g_o[M_ * E_];
__device__ float g_fc[M_ * E4_];

// split-bf16 weight buffers
__device__ __nv_bfloat16 g_wqkv_h[L_ * E_ * E3_], g_wqkv_l[L_ * E_ * E3_];
__device__ __nv_bfloat16 g_wao_h[L_ * E_ * E_],  g_wao_l[L_ * E_ * E_];
__device__ __nv_bfloat16 g_wfc_h[L_ * E_ * E4_], g_wfc_l[L_ * E_ * E4_];
__device__ __nv_bfloat16 g_wmp_h[L_ * E4_ * E_], g_wmp_l[L_ * E4_ * E_];
__device__ __nv_bfloat16 g_wlm_h[E_ * VP_],      g_wlm_l[E_ * VP_];
// split-bf16 activation buffers (A operand), reused
__device__ __nv_bfloat16 g_a_h[M_ * E4_], g_a_l[M_ * E4_];

// ---------------- mma / ldmatrix primitives ----------------
__device__ __forceinline__ void mma16816(float* c, const unsigned* a, const unsigned* b) {
    asm volatile(
        "mma.sync.aligned.m16n8k16.row.col.f32.bf16.bf16.f32 "
        "{%0,%1,%2,%3}, {%4,%5,%6,%7}, {%8,%9}, {%0,%1,%2,%3};"
        : "+f"(c[0]), "+f"(c[1]), "+f"(c[2]), "+f"(c[3])
        : "r"(a[0]), "r"(a[1]), "r"(a[2]), "r"(a[3]), "r"(b[0]), "r"(b[1]));
}
__device__ __forceinline__ void ldsm4(unsigned* r, unsigned addr) {
    asm volatile("ldmatrix.sync.aligned.m8n8.x4.shared.b16 {%0,%1,%2,%3}, [%4];"
                 : "=r"(r[0]), "=r"(r[1]), "=r"(r[2]), "=r"(r[3]) : "r"(addr));
}
__device__ __forceinline__ void ldsm2t(unsigned* r, unsigned addr) {
    asm volatile("ldmatrix.sync.aligned.m8n8.x2.trans.shared.b16 {%0,%1}, [%2];"
                 : "=r"(r[0]), "=r"(r[1]) : "r"(addr));
}

// ---------------- reductions ----------------
__device__ __forceinline__ float wsum(float v) {
#pragma unroll
    for (int o = 16; o; o >>= 1) v += __shfl_xor_sync(0xffffffffu, v, o);
    return v;
}
__device__ __forceinline__ float wmax(float v) {
#pragma unroll
    for (int o = 16; o; o >>= 1) v = fmaxf(v, __shfl_xor_sync(0xffffffffu, v, o));
    return v;
}
__device__ __forceinline__ float blockSum(float v, float* red, float* stat, int tid) {
    __syncthreads();
    v = wsum(v);
    if ((tid & 31) == 0) red[tid >> 5] = v;
    __syncthreads();
    if (tid < 32) {
        float t = (tid < 8) ? red[tid] : 0.f;
#pragma unroll
        for (int o = 4; o; o >>= 1) t += __shfl_xor_sync(0xffffffffu, t, o);
        if (tid == 0) *stat = t;
    }
    __syncthreads();
    return *stat;
}
__device__ __forceinline__ float blockMax(float v, float* red, float* stat, int tid) {
    __syncthreads();
    v = wmax(v);
    if ((tid & 31) == 0) red[tid >> 5] = v;
    __syncthreads();
    if (tid < 32) {
        float t = (tid < 8) ? red[tid] : -3.4e38f;
#pragma unroll
        for (int o = 4; o; o >>= 1) t = fmaxf(t, __shfl_xor_sync(0xffffffffu, t, o));
        if (tid == 0) *stat = t;
    }
    __syncthreads();
    return *stat;
}

// ---------------- split conversions ----------------
union BF4 { __nv_bfloat16 b[4]; uint2 u; };

// n4 = n/4; src length n (multiple of 4)
__global__ __launch_bounds__(256) void k_cvt4(const float4* __restrict__ src,
                                              uint2* __restrict__ dh,
                                              uint2* __restrict__ dl, int n4) {
    int i = blockIdx.x * 256 + threadIdx.x;
    if (i >= n4) return;
    float4 v = src[i];
    BF4 h, l;
    const float* vp = &v.x;
#pragma unroll
    for (int j = 0; j < 4; j++) {
        __nv_bfloat16 hh = __float2bfloat16(vp[j]);
        h.b[j] = hh;
        l.b[j] = __float2bfloat16(vp[j] - __bfloat162float(hh));
    }
    dh[i] = h.u;
    dl[i] = l.u;
}

// pad wlm [E_,V_] -> [E_,VP_]
__global__ __launch_bounds__(256) void k_cvt_pad(const float* __restrict__ src,
                                                 uint2* __restrict__ dh,
                                                 uint2* __restrict__ dl) {
    int i = blockIdx.x * 256 + threadIdx.x;          // index over E_*VP_/4
    if (i >= E_ * VP_ / 4) return;
    int n = (i * 4) % VP_;
    int k = (i * 4) / VP_;
    BF4 h, l;
#pragma unroll
    for (int j = 0; j < 4; j++) {
        float v = (n + j < V_) ? src[(size_t)k * V_ + n + j] : 0.f;
        __nv_bfloat16 hh = __float2bfloat16(v);
        h.b[j] = hh;
        l.b[j] = __float2bfloat16(v - __bfloat162float(hh));
    }
    dh[i] = h.u;
    dl[i] = l.u;
}

// ---------------- embedding ----------------
__global__ __launch_bounds__(256) void k_embed(const int* __restrict__ ids,
                                               const float* __restrict__ wte,
                                               const float* __restrict__ wpe,
                                               float* __restrict__ x) {
    int row = blockIdx.x;
    int s   = row & (S_ - 1);
    int id  = ids[row];
    const float* te = wte + (size_t)id * E_;
    const float* pe = wpe + (size_t)s * E_;
    float* xr = x + (size_t)row * E_;
    for (int e = threadIdx.x; e < E_; e += 256) xr[e] = te[e] + pe[e];
}

// ---------------- layernorm (writes fp32 + split bf16) ----------------
__global__ __launch_bounds__(256) void k_ln(const float* __restrict__ x,
                                            const float* __restrict__ gamma,
                                            const float* __restrict__ beta,
                                            float* __restrict__ out) {
    __shared__ float red[8];
    __shared__ float stat;
    int row = blockIdx.x, tid = threadIdx.x;
    const float* xr = x + (size_t)row * E_;
    float v0 = xr[tid], v1 = xr[tid + 256], v2 = xr[tid + 512];
    float mu = blockSum(v0 + v1 + v2, red, &stat, tid) * (1.0f / E_);
    float d0 = v0 - mu, d1 = v1 - mu, d2 = v2 - mu;
    float var = blockSum(d0 * d0 + d1 * d1 + d2 * d2, red, &stat, tid) * (1.0f / E_);
    float rstd = rsqrtf(var + 1e-6f);
    float* orow = out + (size_t)row * E_;
    orow[tid]       = d0 * rstd * gamma[tid]       + beta[tid];
    orow[tid + 256] = d1 * rstd * gamma[tid + 256] + beta[tid + 256];
    orow[tid + 512] = d2 * rstd * gamma[tid + 512] + beta[tid + 512];
}

// ---------------- split-bf16 tensor-core GEMM ----------------
// C[M,N] = (Ah+Al)[M,K] @ (Bh+Bl)[K,N]  (+bias)(gelu)(+res)
// Ns = stride of B rows (padded); C/res use stride N.
// 128x128 tile, 8 warps of 64x32, BK=16, 3 MMAs per fragment pair.
template <bool BIAS, bool GELU_T, bool RES>
__global__ __launch_bounds__(256) void k_gemm(
    const __nv_bfloat16* __restrict__ Ah, const __nv_bfloat16* __restrict__ Al,
    const __nv_bfloat16* __restrict__ Bh, const __nv_bfloat16* __restrict__ Bl,
    const float* __restrict__ bias, const float* __restrict__ res,
    float* __restrict__ C, int M, int N, int Ns, int K)
{
    __shared__ __nv_bfloat16 AsH[128][24];   // 16 cols + pad -> 48B rows
    __shared__ __nv_bfloat16 AsL[128][24];
    __shared__ __nv_bfloat16 BsH[16][136];   // 128 cols + pad -> 272B rows
    __shared__ __nv_bfloat16 BsL[16][136];

    int tid = threadIdx.x;
    int lane = tid & 31, wid = tid >> 5;
    int wm = (wid & 1) << 6;    // 0 / 64
    int wn = (wid >> 1) << 5;   // 0,32,64,96
    int m0 = blockIdx.x << 7;
    int n0 = blockIdx.y << 7;

    float acc[4][4][4];
#pragma unroll
    for (int i = 0; i < 4; i++)
#pragma unroll
        for (int j = 0; j < 4; j++)
#pragma unroll
            for (int c = 0; c < 4; c++) acc[i][j][c] = 0.f;

    // global->smem copy indices
    int ar = tid >> 1, ac = (tid & 1) << 3;   // A: row 0..127, col 0/8
    int bk = tid >> 4, bs = (tid & 15) << 3;  // B: k 0..15, col seg*8

    const uint4* gAh = (const uint4*)(Ah + (size_t)(m0 + ar) * K + ac);
    const uint4* gAl = (const uint4*)(Al + (size_t)(m0 + ar) * K + ac);
    const uint4* gBh = (const uint4*)(Bh + (size_t)bk * Ns + n0 + bs);
    const uint4* gBl = (const uint4*)(Bl + (size_t)bk * Ns + n0 + bs);
    size_t bstep = (size_t)2 * Ns;   // 16 rows in uint4 units

    unsigned sAh = (unsigned)__cvta_generic_to_shared(&AsH[0][0]);
    unsigned sAl = (unsigned)__cvta_generic_to_shared(&AsL[0][0]);
    unsigned sBh = (unsigned)__cvta_generic_to_shared(&BsH[0][0]);
    unsigned sBl = (unsigned)__cvta_generic_to_shared(&BsL[0][0]);

    int l16 = lane & 15, lh = lane >> 4;
    unsigned aoff = (unsigned)(l16 * 48 + lh * 16);
    unsigned boff = (unsigned)(l16 * 272);

    uint4 rah = gAh[0], ral = gAl[0], rbh = gBh[0], rbl = gBl[0];

    for (int k0 = 0; k0 < K; k0 += 16) {
        *(uint4*)&AsH[ar][ac] = rah;
        *(uint4*)&AsL[ar][ac] = ral;
        *(uint4*)&BsH[bk][bs] = rbh;
        *(uint4*)&BsL[bk][bs] = rbl;
        __syncthreads();

        gAh += 2; gAl += 2; gBh += bstep; gBl += bstep;
        if (k0 + 16 < K) {
            rah = gAh[0]; ral = gAl[0]; rbh = gBh[0]; rbl = gBl[0];
        }

        unsigned afh[4][4], afl[4][4];
#pragma unroll
        for (int i = 0; i < 4; i++) {
            unsigned rbase = (unsigned)((wm + i * 16) * 48) + aoff;
            ldsm4(afh[i], sAh + rbase);
            ldsm4(afl[i], sAl + rbase);
        }
#pragma unroll
        for (int j = 0; j < 4; j++) {
            unsigned cb = boff + (unsigned)((wn + j * 8) * 2);
            unsigned bfh[2], bfl[2];
            ldsm2t(bfh, sBh + cb);
            ldsm2t(bfl, sBl + cb);
#pragma unroll
            for (int i = 0; i < 4; i++) {
                mma16816(acc[i][j], afh[i], bfh);
                mma16816(acc[i][j], afh[i], bfl);
                mma16816(acc[i][j], afl[i], bfh);
            }
        }
        __syncthreads();
    }

    // epilogue
    int g = lane >> 2, tig = lane & 3;
#pragma unroll
    for (int i = 0; i < 4; i++) {
        int mr = m0 + wm + i * 16 + g;
#pragma unroll
        for (int j = 0; j < 4; j++) {
            int nc = n0 + wn + j * 8 + tig * 2;
#pragma unroll
            for (int c = 0; c < 4; c++) {
                int m = mr + (c >> 1) * 8;
                int n = nc + (c & 1);
                if (n < N) {
                    float t = acc[i][j][c];
                    if (BIAS) t += bias[n];
                    if (GELU_T) {
                        float v = t;
                        float cc = 0.7978845608028654f * (v + 0.044715f * v * v * v);
                        t = 0.5f * v * (1.0f + tanhf(cc));
                    }
                    size_t idx = (size_t)m * N + n;
                    if (RES) t += res[idx];
                    C[idx] = t;
                }
            }
        }
    }
}

// ---------------- attention scores ----------------
__global__ __launch_bounds__(256) void k_scores(const float* __restrict__ qkv,
                                                float* __restrict__ sc) {
    int bh = blockIdx.z;
    int b = bh / H_, h = bh % H_;
    int q0 = blockIdx.y << 6;
    int k0 = blockIdx.x << 6;
    int tid = threadIdx.x;
    int tr = tid >> 4, tc = tid & 15;

    float* srow = sc + ((size_t)bh * S_) * S_;

    if (k0 > q0 + 63) {
#pragma unroll
        for (int i = 0; i < 4; i++) {
            int q = q0 + tr * 4 + i;
            float4 mv = make_float4(-10000.f, -10000.f, -10000.f, -10000.f);
            *(float4*)&srow[(size_t)q * S_ + k0 + tc * 4] = mv;
        }
        return;
    }

    __shared__ float Qs[64][65];
    __shared__ float Ks[64][65];
    for (int i = tid; i < 64 * 64; i += 256) {
        int r = i >> 6, c = i & 63;
        Qs[r][c] = qkv[(size_t)(b * S_ + q0 + r) * E3_ + h * D_ + c];
        Ks[r][c] = qkv[(size_t)(b * S_ + k0 + r) * E3_ + E_ + h * D_ + c];
    }
    __syncthreads();

    float acc[4][4];
#pragma unroll
    for (int i = 0; i < 4; i++)
#pragma unroll
        for (int j = 0; j < 4; j++) acc[i][j] = 0.f;

#pragma unroll 4
    for (int d = 0; d < 64; d++) {
        float ra[4], rb[4];
#pragma unroll
        for (int i = 0; i < 4; i++) ra[i] = Qs[tr * 4 + i][d];
#pragma unroll
        for (int j = 0; j < 4; j++) rb[j] = Ks[tc * 4 + j][d];
#pragma unroll
        for (int i = 0; i < 4; i++)
#pragma unroll
            for (int j = 0; j < 4; j++) acc[i][j] = fmaf(ra[i], rb[j], acc[i][j]);
    }

#pragma unroll
    for (int i = 0; i < 4; i++) {
        int q = q0 + tr * 4 + i;
        float4 v;
        float* vp = &v.x;
#pragma unroll
        for (int j = 0; j < 4; j++) {
            int k = k0 + tc * 4 + j;
            vp[j] = (k <= q) ? acc[i][j] * 0.125f : -10000.f;
        }
        *(float4*)&srow[(size_t)q * S_ + k0 + tc * 4] = v;
    }
}

// ---------------- row softmax ----------------
__global__ __launch_bounds__(256) void k_softmax(float* __restrict__ sc) {
    __shared__ float red[8];
    __shared__ float stat;
    int tid = threadIdx.x;
    float* p = sc + (size_t)blockIdx.x * S_;
    float v0 = p[tid], v1 = p[tid + 256], v2 = p[tid + 512], v3 = p[tid + 768];
    float m = blockMax(fmaxf(fmaxf(v0, v1), fmaxf(v2, v3)), red, &stat, tid);
    float e0 = __expf(v0 - m), e1 = __expf(v1 - m), e2 = __expf(v2 - m), e3 = __expf(v3 - m);
    float s = blockSum(e0 + e1 + e2 + e3, red, &stat, tid);
    float inv = 1.0f / s;
    p[tid] = e0 * inv; p[tid + 256] = e1 * inv; p[tid + 512] = e2 * inv; p[tid + 768] = e3 * inv;
}

// ---------------- attn @ V ----------------
__global__ __launch_bounds__(256) void k_av(const float* __restrict__ sc,
                                            const float* __restrict__ qkv,
                                            float* __restrict__ o) {
    int bh = blockIdx.y;
    int b = bh / H_, h = bh % H_;
    int q0 = blockIdx.x << 6;
    int tid = threadIdx.x;
    int tr = tid >> 4, tc = tid & 15;

    __shared__ float Ps[64][65];
    __shared__ float Vs[64][65];

    float acc[4][4];
#pragma unroll
    for (int i = 0; i < 4; i++)
#pragma unroll
        for (int j = 0; j < 4; j++) acc[i][j] = 0.f;

    int nkt = blockIdx.x + 1;
    for (int kt = 0; kt < nkt; kt++) {
        for (int i = tid; i < 64 * 64; i += 256) {
            int r = i >> 6, c = i & 63;
            Ps[r][c] = sc[((size_t)bh * S_ + q0 + r) * S_ + kt * 64 + c];
            Vs[r][c] = qkv[(size_t)(b * S_ + kt * 64 + r) * E3_ + 2 * E_ + h * D_ + c];
        }
        __syncthreads();
#pragma unroll 4
        for (int k = 0; k < 64; k++) {
            float ra[4], rb[4];
#pragma unroll
            for (int i = 0; i < 4; i++) ra[i] = Ps[tr * 4 + i][k];
#pragma unroll
            for (int j = 0; j < 4; j++) rb[j] = Vs[k][tc * 4 + j];
#pragma unroll
            for (int i = 0; i < 4; i++)
#pragma unroll
                for (int j = 0; j < 4; j++) acc[i][j] = fmaf(ra[i], rb[j], acc[i][j]);
        }
        __syncthreads();
    }

#pragma unroll
    for (int i = 0; i < 4; i++) {
        int q = q0 + tr * 4 + i;
        float4 v = make_float4(acc[i][0], acc[i][1], acc[i][2], acc[i][3]);
        *(float4*)&o[(size_t)(b * S_ + q) * E_ + h * D_ + tc * 4] = v;
    }
}

// ---------------- launcher ----------------
static inline void cvt(const float* src, __nv_bfloat16* h, __nv_bfloat16* l, int n) {
    int n4 = n / 4;
    k_cvt4<<<(n4 + 255) / 256, 256>>>((const float4*)src, (uint2*)h, (uint2*)l, n4);
}

extern "C" void kernel_launch(void* const* d_in, const int* in_sizes, int n_in,
                              void* d_out, int out_size) {
    (void)in_sizes; (void)n_in; (void)out_size;
    const int*   ids  = (const int*)  d_in[0];
    const float* wte  = (const float*)d_in[1];
    const float* wpe  = (const float*)d_in[2];
    const float* ln1s = (const float*)d_in[3];
    const float* ln1b = (const float*)d_in[4];
    const float* wqkv = (const float*)d_in[5];
    const float* bqkv = (const float*)d_in[6];
    const float* wao  = (const float*)d_in[7];
    const float* bao  = (const float*)d_in[8];
    const float* ln2s = (const float*)d_in[9];
    const float* ln2b = (const float*)d_in[10];
    const float* wfc  = (const float*)d_in[11];
    const float* bfc  = (const float*)d_in[12];
    const float* wmp  = (const float*)d_in[13];
    const float* bmp  = (const float*)d_in[14];
    const float* lnfs = (const float*)d_in[15];
    const float* lnfb = (const float*)d_in[16];
    const float* wlm  = (const float*)d_in[17];
    float* out = (float*)d_out;

    float *x, *h, *qkv, *sc, *o, *fc;
    cudaGetSymbolAddress((void**)&x,   g_x);
    cudaGetSymbolAddress((void**)&h,   g_h);
    cudaGetSymbolAddress((void**)&qkv, g_qkv);
    cudaGetSymbolAddress((void**)&sc,  g_scores);
    cudaGetSymbolAddress((void**)&o,   g_o);
    cudaGetSymbolAddress((void**)&fc,  g_fc);

    __nv_bfloat16 *wqh, *wql, *waoh, *waol, *wfh, *wfl, *wmh, *wml, *wlh, *wll, *aH, *aL;
    cudaGetSymbolAddress((void**)&wqh, g_wqkv_h);  cudaGetSymbolAddress((void**)&wql, g_wqkv_l);
    cudaGetSymbolAddress((void**)&waoh, g_wao_h);  cudaGetSymbolAddress((void**)&waol, g_wao_l);
    cudaGetSymbolAddress((void**)&wfh, g_wfc_h);   cudaGetSymbolAddress((void**)&wfl, g_wfc_l);
    cudaGetSymbolAddress((void**)&wmh, g_wmp_h);   cudaGetSymbolAddress((void**)&wml, g_wmp_l);
    cudaGetSymbolAddress((void**)&wlh, g_wlm_h);   cudaGetSymbolAddress((void**)&wll, g_wlm_l);
    cudaGetSymbolAddress((void**)&aH, g_a_h);      cudaGetSymbolAddress((void**)&aL, g_a_l);

    // weight conversions (every call; deterministic)
    cvt(wqkv, wqh, wql, L_ * E_ * E3_);
    cvt(wao,  waoh, waol, L_ * E_ * E_);
    cvt(wfc,  wfh, wfl, L_ * E_ * E4_);
    cvt(wmp,  wmh, wml, L_ * E4_ * E_);
    k_cvt_pad<<<(E_ * VP_ / 4 + 255) / 256, 256>>>(wlm, (uint2*)wlh, (uint2*)wll);

    k_embed<<<M_, 256>>>(ids, wte, wpe, x);

    for (int l = 0; l < L_; l++) {
        // --- attention ---
        k_ln<<<M_, 256>>>(x, ln1s + l * E_, ln1b + l * E_, h);
        cvt(h, aH, aL, M_ * E_);
        k_gemm<true, false, false><<<dim3(M_ / 128, E3_ / 128), 256>>>(
            aH, aL, wqh + (size_t)l * E_ * E3_, wql + (size_t)l * E_ * E3_,
            bqkv + l * E3_, nullptr, qkv, M_, E3_, E3_, E_);
        k_scores<<<dim3(S_ / 64, S_ / 64, BH_), 256>>>(qkv, sc);
        k_softmax<<<BH_ * S_, 256>>>(sc);
        k_av<<<dim3(S_ / 64, BH_), 256>>>(sc, qkv, o);
        cvt(o, aH, aL, M_ * E_);
        k_gemm<true, false, true><<<dim3(M_ / 128, E_ / 128), 256>>>(
            aH, aL, waoh + (size_t)l * E_ * E_, waol + (size_t)l * E_ * E_,
            bao + l * E_, x, x, M_, E_, E_, E_);
        // --- MLP ---
        k_ln<<<M_, 256>>>(x, ln2s + l * E_, ln2b + l * E_, h);
        cvt(h, aH, aL, M_ * E_);
        k_gemm<true, true, false><<<dim3(M_ / 128, E4_ / 128), 256>>>(
            aH, aL, wfh + (size_t)l * E_ * E4_, wfl + (size_t)l * E_ * E4_,
            bfc + l * E4_, nullptr, fc, M_, E4_, E4_, E_);
        cvt(fc, aH, aL, M_ * E4_);
        k_gemm<true, false, true><<<dim3(M_ / 128, E_ / 128), 256>>>(
            aH, aL, wmh + (size_t)l * E4_ * E_, wml + (size_t)l * E4_ * E_,
            bmp + l * E_, x, x, M_, E_, E_, E4_);
    }

    // --- final LN + LM head ---
    k_ln<<<M_, 256>>>(x, lnfs, lnfb, h);
    cvt(h, aH, aL, M_ * E_);
    k_gemm<false, false, false><<<dim3(M_ / 128, (VP_) / 128), 256>>>(
        aH, aL, wlh, wll, nullptr, nullptr, out, M_, V_, VP_, E_);
}

// round 6
// speedup vs baseline: 1.0077x; 1.0077x over previous
#include <cuda_runtime.h>
#include <cuda_bf16.h>
#include <math.h>

// GPT-2 small, 4 layers: B=2, S=1024, E=768, H=12, D=64, V=50257
#define B_   2
#define S_   1024
#define E_   768
#define H_   12
#define D_   64
#define L_   4
#define V_   50257
#define VP_  50304          // V padded to multiple of 128
#define M_   (B_ * S_)      // 2048
#define E3_  (3 * E_)       // 2304
#define E4_  (4 * E_)       // 3072
#define BH_  (B_ * H_)      // 24

// ---------------- scratch (allocation-free: device globals) ----------------
__device__ float g_x[M_ * E_];
__device__ float g_h[M_ * E_];
__device__ float g_qkv[M_ * E3_];
__device__ float g_scores[(size_t)BH_ * S_ * S_];
__device__ float g_o[M_ * E_];
__device__ float g_fc[M_ * E4_];

// split-bf16 weight buffers
__device__ __nv_bfloat16 g_wqkv_h[L_ * E_ * E3_], g_wqkv_l[L_ * E_ * E3_];
__device__ __nv_bfloat16 g_wao_h[L_ * E_ * E_],  g_wao_l[L_ * E_ * E_];
__device__ __nv_bfloat16 g_wfc_h[L_ * E_ * E4_], g_wfc_l[L_ * E_ * E4_];
__device__ __nv_bfloat16 g_wmp_h[L_ * E4_ * E_], g_wmp_l[L_ * E4_ * E_];
__device__ __nv_bfloat16 g_wlm_h[E_ * VP_],      g_wlm_l[E_ * VP_];
// split-bf16 activation buffers (A operand), reused
__device__ __nv_bfloat16 g_a_h[M_ * E4_], g_a_l[M_ * E4_];

// ---------------- mma / ldmatrix primitives ----------------
__device__ __forceinline__ void mma16816(float* c, const unsigned* a, const unsigned* b) {
    asm volatile(
        "mma.sync.aligned.m16n8k16.row.col.f32.bf16.bf16.f32 "
        "{%0,%1,%2,%3}, {%4,%5,%6,%7}, {%8,%9}, {%0,%1,%2,%3};"
        : "+f"(c[0]), "+f"(c[1]), "+f"(c[2]), "+f"(c[3])
        : "r"(a[0]), "r"(a[1]), "r"(a[2]), "r"(a[3]), "r"(b[0]), "r"(b[1]));
}
__device__ __forceinline__ void ldsm4(unsigned* r, unsigned addr) {
    asm volatile("ldmatrix.sync.aligned.m8n8.x4.shared.b16 {%0,%1,%2,%3}, [%4];"
                 : "=r"(r[0]), "=r"(r[1]), "=r"(r[2]), "=r"(r[3]) : "r"(addr));
}
__device__ __forceinline__ void ldsm2t(unsigned* r, unsigned addr) {
    asm volatile("ldmatrix.sync.aligned.m8n8.x2.trans.shared.b16 {%0,%1}, [%2];"
                 : "=r"(r[0]), "=r"(r[1]) : "r"(addr));
}

// ---------------- reductions ----------------
__device__ __forceinline__ float wsum(float v) {
#pragma unroll
    for (int o = 16; o; o >>= 1) v += __shfl_xor_sync(0xffffffffu, v, o);
    return v;
}
__device__ __forceinline__ float wmax(float v) {
#pragma unroll
    for (int o = 16; o; o >>= 1) v = fmaxf(v, __shfl_xor_sync(0xffffffffu, v, o));
    return v;
}
__device__ __forceinline__ float blockSum(float v, float* red, float* stat, int tid) {
    __syncthreads();
    v = wsum(v);
    if ((tid & 31) == 0) red[tid >> 5] = v;
    __syncthreads();
    if (tid < 32) {
        float t = (tid < 8) ? red[tid] : 0.f;
#pragma unroll
        for (int o = 4; o; o >>= 1) t += __shfl_xor_sync(0xffffffffu, t, o);
        if (tid == 0) *stat = t;
    }
    __syncthreads();
    return *stat;
}
__device__ __forceinline__ float blockMax(float v, float* red, float* stat, int tid) {
    __syncthreads();
    v = wmax(v);
    if ((tid & 31) == 0) red[tid >> 5] = v;
    __syncthreads();
    if (tid < 32) {
        float t = (tid < 8) ? red[tid] : -3.4e38f;
#pragma unroll
        for (int o = 4; o; o >>= 1) t = fmaxf(t, __shfl_xor_sync(0xffffffffu, t, o));
        if (tid == 0) *stat = t;
    }
    __syncthreads();
    return *stat;
}

// ---------------- split conversions ----------------
union BF4 { __nv_bfloat16 b[4]; uint2 u; };

// n4 = n/4; src length n (multiple of 4)
__global__ __launch_bounds__(256) void k_cvt4(const float4* __restrict__ src,
                                              uint2* __restrict__ dh,
                                              uint2* __restrict__ dl, int n4) {
    int i = blockIdx.x * 256 + threadIdx.x;
    if (i >= n4) return;
    float4 v = src[i];
    BF4 h, l;
    const float* vp = &v.x;
#pragma unroll
    for (int j = 0; j < 4; j++) {
        __nv_bfloat16 hh = __float2bfloat16(vp[j]);
        h.b[j] = hh;
        l.b[j] = __float2bfloat16(vp[j] - __bfloat162float(hh));
    }
    dh[i] = h.u;
    dl[i] = l.u;
}

// pad wlm [E_,V_] -> [E_,VP_]
__global__ __launch_bounds__(256) void k_cvt_pad(const float* __restrict__ src,
                                                 uint2* __restrict__ dh,
                                                 uint2* __restrict__ dl) {
    int i = blockIdx.x * 256 + threadIdx.x;          // index over E_*VP_/4
    if (i >= E_ * VP_ / 4) return;
    int n = (i * 4) % VP_;
    int k = (i * 4) / VP_;
    BF4 h, l;
#pragma unroll
    for (int j = 0; j < 4; j++) {
        float v = (n + j < V_) ? src[(size_t)k * V_ + n + j] : 0.f;
        __nv_bfloat16 hh = __float2bfloat16(v);
        h.b[j] = hh;
        l.b[j] = __float2bfloat16(v - __bfloat162float(hh));
    }
    dh[i] = h.u;
    dl[i] = l.u;
}

// ---------------- embedding ----------------
__global__ __launch_bounds__(256) void k_embed(const int* __restrict__ ids,
                                               const float* __restrict__ wte,
                                               const float* __restrict__ wpe,
                                               float* __restrict__ x) {
    int row = blockIdx.x;
    int s   = row & (S_ - 1);
    int id  = ids[row];
    const float* te = wte + (size_t)id * E_;
    const float* pe = wpe + (size_t)s * E_;
    float* xr = x + (size_t)row * E_;
    for (int e = threadIdx.x; e < E_; e += 256) xr[e] = te[e] + pe[e];
}

// ---------------- layernorm (writes fp32 + split bf16) ----------------
__global__ __launch_bounds__(256) void k_ln(const float* __restrict__ x,
                                            const float* __restrict__ gamma,
                                            const float* __restrict__ beta,
                                            float* __restrict__ out) {
    __shared__ float red[8];
    __shared__ float stat;
    int row = blockIdx.x, tid = threadIdx.x;
    const float* xr = x + (size_t)row * E_;
    float v0 = xr[tid], v1 = xr[tid + 256], v2 = xr[tid + 512];
    float mu = blockSum(v0 + v1 + v2, red, &stat, tid) * (1.0f / E_);
    float d0 = v0 - mu, d1 = v1 - mu, d2 = v2 - mu;
    float var = blockSum(d0 * d0 + d1 * d1 + d2 * d2, red, &stat, tid) * (1.0f / E_);
    float rstd = rsqrtf(var + 1e-6f);
    float* orow = out + (size_t)row * E_;
    orow[tid]       = d0 * rstd * gamma[tid]       + beta[tid];
    orow[tid + 256] = d1 * rstd * gamma[tid + 256] + beta[tid + 256];
    orow[tid + 512] = d2 * rstd * gamma[tid + 512] + beta[tid + 512];
}

// ---------------- split-bf16 tensor-core GEMM ----------------
// C[M,N] = (Ah+Al)[M,K] @ (Bh+Bl)[K,N]  (+bias)(gelu)(+res)
// Ns = stride of B rows (padded); C/res use stride N.
// 128x128 tile, 8 warps of 64x32, BK=16, 3 MMAs per fragment pair.
template <bool BIAS, bool GELU_T, bool RES>
__global__ __launch_bounds__(256) void k_gemm(
    const __nv_bfloat16* __restrict__ Ah, const __nv_bfloat16* __restrict__ Al,
    const __nv_bfloat16* __restrict__ Bh, const __nv_bfloat16* __restrict__ Bl,
    const float* __restrict__ bias, const float* __restrict__ res,
    float* __restrict__ C, int M, int N, int Ns, int K)
{
    __shared__ __nv_bfloat16 AsH[128][24];   // 16 cols + pad -> 48B rows
    __shared__ __nv_bfloat16 AsL[128][24];
    __shared__ __nv_bfloat16 BsH[16][136];   // 128 cols + pad -> 272B rows
    __shared__ __nv_bfloat16 BsL[16][136];

    int tid = threadIdx.x;
    int lane = tid & 31, wid = tid >> 5;
    int wm = (wid & 1) << 6;    // 0 / 64
    int wn = (wid >> 1) << 5;   // 0,32,64,96
    int m0 = blockIdx.x << 7;
    int n0 = blockIdx.y << 7;

    float acc[4][4][4];
#pragma unroll
    for (int i = 0; i < 4; i++)
#pragma unroll
        for (int j = 0; j < 4; j++)
#pragma unroll
            for (int c = 0; c < 4; c++) acc[i][j][c] = 0.f;

    // global->smem copy indices
    int ar = tid >> 1, ac = (tid & 1) << 3;   // A: row 0..127, col 0/8
    int bk = tid >> 4, bs = (tid & 15) << 3;  // B: k 0..15, col seg*8

    const uint4* gAh = (const uint4*)(Ah + (size_t)(m0 + ar) * K + ac);
    const uint4* gAl = (const uint4*)(Al + (size_t)(m0 + ar) * K + ac);
    const uint4* gBh = (const uint4*)(Bh + (size_t)bk * Ns + n0 + bs);
    const uint4* gBl = (const uint4*)(Bl + (size_t)bk * Ns + n0 + bs);
    size_t bstep = (size_t)2 * Ns;   // 16 rows in uint4 units

    unsigned sAh = (unsigned)__cvta_generic_to_shared(&AsH[0][0]);
    unsigned sAl = (unsigned)__cvta_generic_to_shared(&AsL[0][0]);
    unsigned sBh = (unsigned)__cvta_generic_to_shared(&BsH[0][0]);
    unsigned sBl = (unsigned)__cvta_generic_to_shared(&BsL[0][0]);

    int l16 = lane & 15, lh = lane >> 4;
    unsigned aoff = (unsigned)(l16 * 48 + lh * 16);
    unsigned boff = (unsigned)(l16 * 272);

    uint4 rah = gAh[0], ral = gAl[0], rbh = gBh[0], rbl = gBl[0];

    for (int k0 = 0; k0 < K; k0 += 16) {
        *(uint4*)&AsH[ar][ac] = rah;
        *(uint4*)&AsL[ar][ac] = ral;
        *(uint4*)&BsH[bk][bs] = rbh;
        *(uint4*)&BsL[bk][bs] = rbl;
        __syncthreads();

        gAh += 2; gAl += 2; gBh += bstep; gBl += bstep;
        if (k0 + 16 < K) {
            rah = gAh[0]; ral = gAl[0]; rbh = gBh[0]; rbl = gBl[0];
        }

        unsigned afh[4][4], afl[4][4];
#pragma unroll
        for (int i = 0; i < 4; i++) {
            unsigned rbase = (unsigned)((wm + i * 16) * 48) + aoff;
            ldsm4(afh[i], sAh + rbase);
            ldsm4(afl[i], sAl + rbase);
        }
#pragma unroll
        for (int j = 0; j < 4; j++) {
            unsigned cb = boff + (unsigned)((wn + j * 8) * 2);
            unsigned bfh[2], bfl[2];
            ldsm2t(bfh, sBh + cb);
            ldsm2t(bfl, sBl + cb);
#pragma unroll
            for (int i = 0; i < 4; i++) {
                mma16816(acc[i][j], afh[i], bfh);
                mma16816(acc[i][j], afh[i], bfl);
                mma16816(acc[i][j], afl[i], bfh);
            }
        }
        __syncthreads();
    }

    // epilogue
    int g = lane >> 2, tig = lane & 3;
#pragma unroll
    for (int i = 0; i < 4; i++) {
        int mr = m0 + wm + i * 16 + g;
#pragma unroll
        for (int j = 0; j < 4; j++) {
            int nc = n0 + wn + j * 8 + tig * 2;
#pragma unroll
            for (int c = 0; c < 4; c++) {
                int m = mr + (c >> 1) * 8;
                int n = nc + (c & 1);
                if (n < N) {
                    float t = acc[i][j][c];
                    if (BIAS) t += bias[n];
                    if (GELU_T) {
                        float v = t;
                        float cc = 0.7978845608028654f * (v + 0.044715f * v * v * v);
                        t = 0.5f * v * (1.0f + tanhf(cc));
                    }
                    size_t idx = (size_t)m * N + n;
                    if (RES) t += res[idx];
                    C[idx] = t;
                }
            }
        }
    }
}

// ---------------- attention scores ----------------
__global__ __launch_bounds__(256) void k_scores(const float* __restrict__ qkv,
                                                float* __restrict__ sc) {
    int bh = blockIdx.z;
    int b = bh / H_, h = bh % H_;
    int q0 = blockIdx.y << 6;
    int k0 = blockIdx.x << 6;
    int tid = threadIdx.x;
    int tr = tid >> 4, tc = tid & 15;

    float* srow = sc + ((size_t)bh * S_) * S_;

    if (k0 > q0 + 63) {
#pragma unroll
        for (int i = 0; i < 4; i++) {
            int q = q0 + tr * 4 + i;
            float4 mv = make_float4(-10000.f, -10000.f, -10000.f, -10000.f);
            *(float4*)&srow[(size_t)q * S_ + k0 + tc * 4] = mv;
        }
        return;
    }

    __shared__ float Qs[64][65];
    __shared__ float Ks[64][65];
    for (int i = tid; i < 64 * 64; i += 256) {
        int r = i >> 6, c = i & 63;
        Qs[r][c] = qkv[(size_t)(b * S_ + q0 + r) * E3_ + h * D_ + c];
        Ks[r][c] = qkv[(size_t)(b * S_ + k0 + r) * E3_ + E_ + h * D_ + c];
    }
    __syncthreads();

    float acc[4][4];
#pragma unroll
    for (int i = 0; i < 4; i++)
#pragma unroll
        for (int j = 0; j < 4; j++) acc[i][j] = 0.f;

#pragma unroll 4
    for (int d = 0; d < 64; d++) {
        float ra[4], rb[4];
#pragma unroll
        for (int i = 0; i < 4; i++) ra[i] = Qs[tr * 4 + i][d];
#pragma unroll
        for (int j = 0; j < 4; j++) rb[j] = Ks[tc * 4 + j][d];
#pragma unroll
        for (int i = 0; i < 4; i++)
#pragma unroll
            for (int j = 0; j < 4; j++) acc[i][j] = fmaf(ra[i], rb[j], acc[i][j]);
    }

#pragma unroll
    for (int i = 0; i < 4; i++) {
        int q = q0 + tr * 4 + i;
        float4 v;
        float* vp = &v.x;
#pragma unroll
        for (int j = 0; j < 4; j++) {
            int k = k0 + tc * 4 + j;
            vp[j] = (k <= q) ? acc[i][j] * 0.125f : -10000.f;
        }
        *(float4*)&srow[(size_t)q * S_ + k0 + tc * 4] = v;
    }
}

// ---------------- row softmax ----------------
__global__ __launch_bounds__(256) void k_softmax(float* __restrict__ sc) {
    __shared__ float red[8];
    __shared__ float stat;
    int tid = threadIdx.x;
    float* p = sc + (size_t)blockIdx.x * S_;
    float v0 = p[tid], v1 = p[tid + 256], v2 = p[tid + 512], v3 = p[tid + 768];
    float m = blockMax(fmaxf(fmaxf(v0, v1), fmaxf(v2, v3)), red, &stat, tid);
    float e0 = __expf(v0 - m), e1 = __expf(v1 - m), e2 = __expf(v2 - m), e3 = __expf(v3 - m);
    float s = blockSum(e0 + e1 + e2 + e3, red, &stat, tid);
    float inv = 1.0f / s;
    p[tid] = e0 * inv; p[tid + 256] = e1 * inv; p[tid + 512] = e2 * inv; p[tid + 768] = e3 * inv;
}

// ---------------- attn @ V ----------------
__global__ __launch_bounds__(256) void k_av(const float* __restrict__ sc,
                                            const float* __restrict__ qkv,
                                            float* __restrict__ o) {
    int bh = blockIdx.y;
    int b = bh / H_, h = bh % H_;
    int q0 = blockIdx.x << 6;
    int tid = threadIdx.x;
    int tr = tid >> 4, tc = tid & 15;

    __shared__ float Ps[64][65];
    __shared__ float Vs[64][65];

    float acc[4][4];
#pragma unroll
    for (int i = 0; i < 4; i++)
#pragma unroll
        for (int j = 0; j < 4; j++) acc[i][j] = 0.f;

    int nkt = blockIdx.x + 1;
    for (int kt = 0; kt < nkt; kt++) {
        for (int i = tid; i < 64 * 64; i += 256) {
            int r = i >> 6, c = i & 63;
            Ps[r][c] = sc[((size_t)bh * S_ + q0 + r) * S_ + kt * 64 + c];
            Vs[r][c] = qkv[(size_t)(b * S_ + kt * 64 + r) * E3_ + 2 * E_ + h * D_ + c];
        }
        __syncthreads();
#pragma unroll 4
        for (int k = 0; k < 64; k++) {
            float ra[4], rb[4];
#pragma unroll
            for (int i = 0; i < 4; i++) ra[i] = Ps[tr * 4 + i][k];
#pragma unroll
            for (int j = 0; j < 4; j++) rb[j] = Vs[k][tc * 4 + j];
#pragma unroll
            for (int i = 0; i < 4; i++)
#pragma unroll
                for (int j = 0; j < 4; j++) acc[i][j] = fmaf(ra[i], rb[j], acc[i][j]);
        }
        __syncthreads();
    }

#pragma unroll
    for (int i = 0; i < 4; i++) {
        int q = q0 + tr * 4 + i;
        float4 v = make_float4(acc[i][0], acc[i][1], acc[i][2], acc[i][3]);
        *(float4*)&o[(size_t)(b * S_ + q) * E_ + h * D_ + tc * 4] = v;
    }
}

// ---------------- launcher ----------------
static inline void cvt(const float* src, __nv_bfloat16* h, __nv_bfloat16* l, int n) {
    int n4 = n / 4;
    k_cvt4<<<(n4 + 255) / 256, 256>>>((const float4*)src, (uint2*)h, (uint2*)l, n4);
}

extern "C" void kernel_launch(void* const* d_in, const int* in_sizes, int n_in,
                              void* d_out, int out_size) {
    (void)in_sizes; (void)n_in; (void)out_size;
    const int*   ids  = (const int*)  d_in[0];
    const float* wte  = (const float*)d_in[1];
    const float* wpe  = (const float*)d_in[2];
    const float* ln1s = (const float*)d_in[3];
    const float* ln1b = (const float*)d_in[4];
    const float* wqkv = (const float*)d_in[5];
    const float* bqkv = (const float*)d_in[6];
    const float* wao  = (const float*)d_in[7];
    const float* bao  = (const float*)d_in[8];
    const float* ln2s = (const float*)d_in[9];
    const float* ln2b = (const float*)d_in[10];
    const float* wfc  = (const float*)d_in[11];
    const float* bfc  = (const float*)d_in[12];
    const float* wmp  = (const float*)d_in[13];
    const float* bmp  = (const float*)d_in[14];
    const float* lnfs = (const float*)d_in[15];
    const float* lnfb = (const float*)d_in[16];
    const float* wlm  = (const float*)d_in[17];
    float* out = (float*)d_out;

    float *x, *h, *qkv, *sc, *o, *fc;
    cudaGetSymbolAddress((void**)&x,   g_x);
    cudaGetSymbolAddress((void**)&h,   g_h);
    cudaGetSymbolAddress((void**)&qkv, g_qkv);
    cudaGetSymbolAddress((void**)&sc,  g_scores);
    cudaGetSymbolAddress((void**)&o,   g_o);
    cudaGetSymbolAddress((void**)&fc,  g_fc);

    __nv_bfloat16 *wqh, *wql, *waoh, *waol, *wfh, *wfl, *wmh, *wml, *wlh, *wll, *aH, *aL;
    cudaGetSymbolAddress((void**)&wqh, g_wqkv_h);  cudaGetSymbolAddress((void**)&wql, g_wqkv_l);
    cudaGetSymbolAddress((void**)&waoh, g_wao_h);  cudaGetSymbolAddress((void**)&waol, g_wao_l);
    cudaGetSymbolAddress((void**)&wfh, g_wfc_h);   cudaGetSymbolAddress((void**)&wfl, g_wfc_l);
    cudaGetSymbolAddress((void**)&wmh, g_wmp_h);   cudaGetSymbolAddress((void**)&wml, g_wmp_l);
    cudaGetSymbolAddress((void**)&wlh, g_wlm_h);   cudaGetSymbolAddress((void**)&wll, g_wlm_l);
    cudaGetSymbolAddress((void**)&aH, g_a_h);      cudaGetSymbolAddress((void**)&aL, g_a_l);

    // weight conversions (every call; deterministic)
    cvt(wqkv, wqh, wql, L_ * E_ * E3_);
    cvt(wao,  waoh, waol, L_ * E_ * E_);
    cvt(wfc,  wfh, wfl, L_ * E_ * E4_);
    cvt(wmp,  wmh, wml, L_ * E4_ * E_);
    k_cvt_pad<<<(E_ * VP_ / 4 + 255) / 256, 256>>>(wlm, (uint2*)wlh, (uint2*)wll);

    k_embed<<<M_, 256>>>(ids, wte, wpe, x);

    for (int l = 0; l < L_; l++) {
        // --- attention ---
        k_ln<<<M_, 256>>>(x, ln1s + l * E_, ln1b + l * E_, h);
        cvt(h, aH, aL, M_ * E_);
        k_gemm<true, false, false><<<dim3(M_ / 128, E3_ / 128), 256>>>(
            aH, aL, wqh + (size_t)l * E_ * E3_, wql + (size_t)l * E_ * E3_,
            bqkv + l * E3_, nullptr, qkv, M_, E3_, E3_, E_);
        k_scores<<<dim3(S_ / 64, S_ / 64, BH_), 256>>>(qkv, sc);
        k_softmax<<<BH_ * S_, 256>>>(sc);
        k_av<<<dim3(S_ / 64, BH_), 256>>>(sc, qkv, o);
        cvt(o, aH, aL, M_ * E_);
        k_gemm<true, false, true><<<dim3(M_ / 128, E_ / 128), 256>>>(
            aH, aL, waoh + (size_t)l * E_ * E_, waol + (size_t)l * E_ * E_,
            bao + l * E_, x, x, M_, E_, E_, E_);
        // --- MLP ---
        k_ln<<<M_, 256>>>(x, ln2s + l * E_, ln2b + l * E_, h);
        cvt(h, aH, aL, M_ * E_);
        k_gemm<true, true, false><<<dim3(M_ / 128, E4_ / 128), 256>>>(
            aH, aL, wfh + (size_t)l * E_ * E4_, wfl + (size_t)l * E_ * E4_,
            bfc + l * E4_, nullptr, fc, M_, E4_, E4_, E_);
        cvt(fc, aH, aL, M_ * E4_);
        k_gemm<true, false, true><<<dim3(M_ / 128, E_ / 128), 256>>>(
            aH, aL, wmh + (size_t)l * E4_ * E_, wml + (size_t)l * E4_ * E_,
            bmp + l * E_, x, x, M_, E_, E_, E4_);
    }

    // --- final LN + LM head ---
    k_ln<<<M_, 256>>>(x, lnfs, lnfb, h);
    cvt(h, aH, aL, M_ * E_);
    k_gemm<false, false, false><<<dim3(M_ / 128, (VP_) / 128), 256>>>(
        aH, aL, wlh, wll, nullptr, nullptr, out, M_, V_, VP_, E_);
}

// round 7
// speedup vs baseline: 1.3709x; 1.3604x over previous
#include <cuda_runtime.h>
#include <cuda_bf16.h>
#include <math.h>

// GPT-2 small, 4 layers: B=2, S=1024, E=768, H=12, D=64, V=50257
#define B_   2
#define S_   1024
#define E_   768
#define H_   12
#define D_   64
#define L_   4
#define V_   50257
#define VP_  50304          // V padded to multiple of 128
#define M_   (B_ * S_)      // 2048
#define E3_  (3 * E_)       // 2304
#define E4_  (4 * E_)       // 3072
#define BH_  (B_ * H_)      // 24

// GEMM pipeline config
#define STG          4
#define STAGE_BYTES  20992      // AH 6144 | AL 6144 | BH 4352 | BL 4352
#define OFF_AH       0
#define OFF_AL       6144
#define OFF_BH       12288
#define OFF_BL       16640
#define GEMM_SMEM    (STG * STAGE_BYTES)   // 83968

// ---------------- scratch (allocation-free: device globals) ----------------
__device__ float g_x[M_ * E_];
__device__ float g_qkv[M_ * E3_];
__device__ float g_scores[(size_t)BH_ * S_ * S_];

// split-bf16 weights
__device__ __nv_bfloat16 g_wqkv_h[L_ * E_ * E3_], g_wqkv_l[L_ * E_ * E3_];
__device__ __nv_bfloat16 g_wao_h[L_ * E_ * E_],  g_wao_l[L_ * E_ * E_];
__device__ __nv_bfloat16 g_wfc_h[L_ * E_ * E4_], g_wfc_l[L_ * E_ * E4_];
__device__ __nv_bfloat16 g_wmp_h[L_ * E4_ * E_], g_wmp_l[L_ * E4_ * E_];
__device__ __nv_bfloat16 g_wlm_h[E_ * VP_],      g_wlm_l[E_ * VP_];
// split-bf16 activations
__device__ __nv_bfloat16 g_a_h[M_ * E_],  g_a_l[M_ * E_];    // LN / attn-out
__device__ __nv_bfloat16 g_b_h[M_ * E4_], g_b_l[M_ * E4_];   // FC output

// ---------------- primitives ----------------
__device__ __forceinline__ void mma16816(float* c, const unsigned* a, const unsigned* b) {
    asm volatile(
        "mma.sync.aligned.m16n8k16.row.col.f32.bf16.bf16.f32 "
        "{%0,%1,%2,%3}, {%4,%5,%6,%7}, {%8,%9}, {%0,%1,%2,%3};"
        : "+f"(c[0]), "+f"(c[1]), "+f"(c[2]), "+f"(c[3])
        : "r"(a[0]), "r"(a[1]), "r"(a[2]), "r"(a[3]), "r"(b[0]), "r"(b[1]));
}
__device__ __forceinline__ void ldsm4(unsigned* r, unsigned addr) {
    asm volatile("ldmatrix.sync.aligned.m8n8.x4.shared.b16 {%0,%1,%2,%3}, [%4];"
                 : "=r"(r[0]), "=r"(r[1]), "=r"(r[2]), "=r"(r[3]) : "r"(addr));
}
__device__ __forceinline__ void ldsm2t(unsigned* r, unsigned addr) {
    asm volatile("ldmatrix.sync.aligned.m8n8.x2.trans.shared.b16 {%0,%1}, [%2];"
                 : "=r"(r[0]), "=r"(r[1]) : "r"(addr));
}
__device__ __forceinline__ void cpa16(unsigned dst, const void* src) {
    asm volatile("cp.async.cg.shared.global [%0], [%1], 16;" :: "r"(dst), "l"(src));
}
__device__ __forceinline__ void cpa_commit() {
    asm volatile("cp.async.commit_group;");
}

// ---------------- reductions ----------------
__device__ __forceinline__ float wsum(float v) {
#pragma unroll
    for (int o = 16; o; o >>= 1) v += __shfl_xor_sync(0xffffffffu, v, o);
    return v;
}
__device__ __forceinline__ float wmax(float v) {
#pragma unroll
    for (int o = 16; o; o >>= 1) v = fmaxf(v, __shfl_xor_sync(0xffffffffu, v, o));
    return v;
}
__device__ __forceinline__ float blockSum(float v, float* red, float* stat, int tid) {
    __syncthreads();
    v = wsum(v);
    if ((tid & 31) == 0) red[tid >> 5] = v;
    __syncthreads();
    if (tid < 32) {
        float t = (tid < 8) ? red[tid] : 0.f;
#pragma unroll
        for (int o = 4; o; o >>= 1) t += __shfl_xor_sync(0xffffffffu, t, o);
        if (tid == 0) *stat = t;
    }
    __syncthreads();
    return *stat;
}
__device__ __forceinline__ float blockMax(float v, float* red, float* stat, int tid) {
    __syncthreads();
    v = wmax(v);
    if ((tid & 31) == 0) red[tid >> 5] = v;
    __syncthreads();
    if (tid < 32) {
        float t = (tid < 8) ? red[tid] : -3.4e38f;
#pragma unroll
        for (int o = 4; o; o >>= 1) t = fmaxf(t, __shfl_xor_sync(0xffffffffu, t, o));
        if (tid == 0) *stat = t;
    }
    __syncthreads();
    return *stat;
}

// ---------------- split conversions (weights only) ----------------
union BF4 { __nv_bfloat16 b[4]; uint2 u; };

__global__ __launch_bounds__(256) void k_cvt4(const float4* __restrict__ src,
                                              uint2* __restrict__ dh,
                                              uint2* __restrict__ dl, int n4) {
    int i = (blockIdx.x * 256 + threadIdx.x) * 2;
#pragma unroll
    for (int u = 0; u < 2; u++, i++) {
        if (i >= n4) return;
        float4 v = src[i];
        BF4 h, l;
        const float* vp = &v.x;
#pragma unroll
        for (int j = 0; j < 4; j++) {
            __nv_bfloat16 hh = __float2bfloat16(vp[j]);
            h.b[j] = hh;
            l.b[j] = __float2bfloat16(vp[j] - __bfloat162float(hh));
        }
        dh[i] = h.u;
        dl[i] = l.u;
    }
}

__global__ __launch_bounds__(256) void k_cvt_pad(const float* __restrict__ src,
                                                 uint2* __restrict__ dh,
                                                 uint2* __restrict__ dl) {
    int i = (blockIdx.x * 256 + threadIdx.x) * 2;
#pragma unroll
    for (int u = 0; u < 2; u++, i++) {
        if (i >= E_ * VP_ / 4) return;
        int n = (i * 4) % VP_;
        int k = (i * 4) / VP_;
        BF4 h, l;
#pragma unroll
        for (int j = 0; j < 4; j++) {
            float v = (n + j < V_) ? src[(size_t)k * V_ + n + j] : 0.f;
            __nv_bfloat16 hh = __float2bfloat16(v);
            h.b[j] = hh;
            l.b[j] = __float2bfloat16(v - __bfloat162float(hh));
        }
        dh[i] = h.u;
        dl[i] = l.u;
    }
}

// ---------------- embedding ----------------
__global__ __launch_bounds__(256) void k_embed(const int* __restrict__ ids,
                                               const float* __restrict__ wte,
                                               const float* __restrict__ wpe,
                                               float* __restrict__ x) {
    int row = blockIdx.x;
    int s   = row & (S_ - 1);
    int id  = ids[row];
    const float* te = wte + (size_t)id * E_;
    const float* pe = wpe + (size_t)s * E_;
    float* xr = x + (size_t)row * E_;
    for (int e = threadIdx.x; e < E_; e += 256) xr[e] = te[e] + pe[e];
}

// ---------------- layernorm -> split bf16 ----------------
__global__ __launch_bounds__(256) void k_ln_split(const float* __restrict__ x,
                                                  const float* __restrict__ gamma,
                                                  const float* __restrict__ beta,
                                                  __nv_bfloat16* __restrict__ oh,
                                                  __nv_bfloat16* __restrict__ ol) {
    __shared__ float red[8];
    __shared__ float stat;
    int row = blockIdx.x, tid = threadIdx.x;
    const float* xr = x + (size_t)row * E_;
    float v0 = xr[tid], v1 = xr[tid + 256], v2 = xr[tid + 512];
    float mu = blockSum(v0 + v1 + v2, red, &stat, tid) * (1.0f / E_);
    float d0 = v0 - mu, d1 = v1 - mu, d2 = v2 - mu;
    float var = blockSum(d0 * d0 + d1 * d1 + d2 * d2, red, &stat, tid) * (1.0f / E_);
    float rstd = rsqrtf(var + 1e-6f);
    size_t base = (size_t)row * E_;
#pragma unroll
    for (int u = 0; u < 3; u++) {
        int e = tid + u * 256;
        float d = (u == 0) ? d0 : (u == 1) ? d1 : d2;
        float y = d * rstd * gamma[e] + beta[e];
        __nv_bfloat16 hh = __float2bfloat16(y);
        oh[base + e] = hh;
        ol[base + e] = __float2bfloat16(y - __bfloat162float(hh));
    }
}

// ---------------- pipelined split-bf16 tensor-core GEMM ----------------
// C[M,N] = (Ah+Al)[M,K] @ (Bh+Bl)[K,N]  (+bias)(gelu)(+res | split-out)
// 128x128 tile, 8 warps 64x32, BK=16, 4-stage cp.async ring in dynamic smem.
template <bool BIAS, bool GELU_T, bool RES, bool SPLITOUT>
__global__ __launch_bounds__(256) void k_gemm(
    const __nv_bfloat16* __restrict__ Ah, const __nv_bfloat16* __restrict__ Al,
    const __nv_bfloat16* __restrict__ Bh, const __nv_bfloat16* __restrict__ Bl,
    const float* __restrict__ bias, const float* __restrict__ res,
    float* __restrict__ C,
    __nv_bfloat16* __restrict__ Ch, __nv_bfloat16* __restrict__ Cl,
    int M, int N, int Ns, int K)
{
    extern __shared__ char sm_[];
    unsigned sbase = (unsigned)__cvta_generic_to_shared(sm_);

    int tid = threadIdx.x;
    int lane = tid & 31, wid = tid >> 5;
    int wm = (wid & 1) << 6;
    int wn = (wid >> 1) << 5;
    int m0 = blockIdx.x << 7;
    int n0 = blockIdx.y << 7;

    // cp.async source/dest indexing
    int ar = tid >> 1;             // A row 0..127
    unsigned acB = (tid & 1) << 4; // A col byte 0/16
    int bk = tid >> 4;             // B k 0..15
    unsigned bsB = (tid & 15) << 4;
    unsigned aoffS = (unsigned)(ar * 48) + acB;
    unsigned boffS = (unsigned)(bk * 272) + bsB;

    const char* gAh = (const char*)(Ah + (size_t)(m0 + ar) * K) + acB;
    const char* gAl = (const char*)(Al + (size_t)(m0 + ar) * K) + acB;
    const char* gBh = (const char*)(Bh + (size_t)bk * Ns + n0) + bsB;
    const char* gBl = (const char*)(Bl + (size_t)bk * Ns + n0) + bsB;
    size_t bStageB = (size_t)32 * Ns;   // bytes per 16 k-rows

    int nk = K >> 4;

    // prologue: issue STG-1 stages
#pragma unroll
    for (int s = 0; s < STG - 1; s++) {
        unsigned so = sbase + s * STAGE_BYTES;
        cpa16(so + OFF_AH + aoffS, gAh + (size_t)s * 32);
        cpa16(so + OFF_AL + aoffS, gAl + (size_t)s * 32);
        cpa16(so + OFF_BH + boffS, gBh + (size_t)s * bStageB);
        cpa16(so + OFF_BL + boffS, gBl + (size_t)s * bStageB);
        cpa_commit();
    }

    float acc[4][4][4];
#pragma unroll
    for (int i = 0; i < 4; i++)
#pragma unroll
        for (int j = 0; j < 4; j++)
#pragma unroll
            for (int c = 0; c < 4; c++) acc[i][j][c] = 0.f;

    int l16 = lane & 15, lh = lane >> 4;
    unsigned aoffL = (unsigned)(l16 * 48 + lh * 16);
    unsigned boffL = (unsigned)(l16 * 272);

    for (int ks = 0; ks < nk; ks++) {
        asm volatile("cp.async.wait_group %0;" :: "n"(STG - 2));
        __syncthreads();
        unsigned so = sbase + (ks & (STG - 1)) * STAGE_BYTES;

        unsigned afh[4][4], afl[4][4];
#pragma unroll
        for (int i = 0; i < 4; i++) {
            unsigned rbase = (unsigned)((wm + i * 16) * 48) + aoffL;
            ldsm4(afh[i], so + OFF_AH + rbase);
            ldsm4(afl[i], so + OFF_AL + rbase);
        }
#pragma unroll
        for (int j = 0; j < 4; j++) {
            unsigned cb = boffL + (unsigned)((wn + j * 8) * 2);
            unsigned bfh[2], bfl[2];
            ldsm2t(bfh, so + OFF_BH + cb);
            ldsm2t(bfl, so + OFF_BL + cb);
#pragma unroll
            for (int i = 0; i < 4; i++) {
                mma16816(acc[i][j], afh[i], bfh);
                mma16816(acc[i][j], afh[i], bfl);
                mma16816(acc[i][j], afl[i], bfh);
            }
        }

        int s2 = ks + STG - 1;
        if (s2 < nk) {
            unsigned so2 = sbase + (s2 & (STG - 1)) * STAGE_BYTES;
            cpa16(so2 + OFF_AH + aoffS, gAh + (size_t)s2 * 32);
            cpa16(so2 + OFF_AL + aoffS, gAl + (size_t)s2 * 32);
            cpa16(so2 + OFF_BH + boffS, gBh + (size_t)s2 * bStageB);
            cpa16(so2 + OFF_BL + boffS, gBl + (size_t)s2 * bStageB);
        }
        cpa_commit();
    }

    // epilogue
    int g = lane >> 2, tig = lane & 3;
#pragma unroll
    for (int i = 0; i < 4; i++) {
        int mr = m0 + wm + i * 16 + g;
#pragma unroll
        for (int j = 0; j < 4; j++) {
            int nc = n0 + wn + j * 8 + tig * 2;
#pragma unroll
            for (int c = 0; c < 4; c++) {
                int m = mr + (c >> 1) * 8;
                int n = nc + (c & 1);
                if (n < N) {
                    float t = acc[i][j][c];
                    if (BIAS) t += bias[n];
                    if (GELU_T) {
                        float v = t;
                        float cc = 0.7978845608028654f * (v + 0.044715f * v * v * v);
                        t = 0.5f * v * (1.0f + tanhf(cc));
                    }
                    size_t idx = (size_t)m * N + n;
                    if (SPLITOUT) {
                        __nv_bfloat16 hh = __float2bfloat16(t);
                        Ch[idx] = hh;
                        Cl[idx] = __float2bfloat16(t - __bfloat162float(hh));
                    } else {
                        if (RES) t += res[idx];
                        C[idx] = t;
                    }
                }
            }
        }
    }
}

// ---------------- attention scores ----------------
__global__ __launch_bounds__(256) void k_scores(const float* __restrict__ qkv,
                                                float* __restrict__ sc) {
    int bh = blockIdx.z;
    int b = bh / H_, h = bh % H_;
    int q0 = blockIdx.y << 6;
    int k0 = blockIdx.x << 6;
    int tid = threadIdx.x;
    int tr = tid >> 4, tc = tid & 15;

    float* srow = sc + ((size_t)bh * S_) * S_;

    if (k0 > q0 + 63) {
#pragma unroll
        for (int i = 0; i < 4; i++) {
            int q = q0 + tr * 4 + i;
            float4 mv = make_float4(-10000.f, -10000.f, -10000.f, -10000.f);
            *(float4*)&srow[(size_t)q * S_ + k0 + tc * 4] = mv;
        }
        return;
    }

    __shared__ float Qs[64][65];
    __shared__ float Ks[64][65];
    for (int i = tid; i < 64 * 64; i += 256) {
        int r = i >> 6, c = i & 63;
        Qs[r][c] = qkv[(size_t)(b * S_ + q0 + r) * E3_ + h * D_ + c];
        Ks[r][c] = qkv[(size_t)(b * S_ + k0 + r) * E3_ + E_ + h * D_ + c];
    }
    __syncthreads();

    float acc[4][4];
#pragma unroll
    for (int i = 0; i < 4; i++)
#pragma unroll
        for (int j = 0; j < 4; j++) acc[i][j] = 0.f;

#pragma unroll 4
    for (int d = 0; d < 64; d++) {
        float ra[4], rb[4];
#pragma unroll
        for (int i = 0; i < 4; i++) ra[i] = Qs[tr * 4 + i][d];
#pragma unroll
        for (int j = 0; j < 4; j++) rb[j] = Ks[tc * 4 + j][d];
#pragma unroll
        for (int i = 0; i < 4; i++)
#pragma unroll
            for (int j = 0; j < 4; j++) acc[i][j] = fmaf(ra[i], rb[j], acc[i][j]);
    }

#pragma unroll
    for (int i = 0; i < 4; i++) {
        int q = q0 + tr * 4 + i;
        float4 v;
        float* vp = &v.x;
#pragma unroll
        for (int j = 0; j < 4; j++) {
            int k = k0 + tc * 4 + j;
            vp[j] = (k <= q) ? acc[i][j] * 0.125f : -10000.f;
        }
        *(float4*)&srow[(size_t)q * S_ + k0 + tc * 4] = v;
    }
}

// ---------------- row softmax ----------------
__global__ __launch_bounds__(256) void k_softmax(float* __restrict__ sc) {
    __shared__ float red[8];
    __shared__ float stat;
    int tid = threadIdx.x;
    float* p = sc + (size_t)blockIdx.x * S_;
    float v0 = p[tid], v1 = p[tid + 256], v2 = p[tid + 512], v3 = p[tid + 768];
    float m = blockMax(fmaxf(fmaxf(v0, v1), fmaxf(v2, v3)), red, &stat, tid);
    float e0 = __expf(v0 - m), e1 = __expf(v1 - m), e2 = __expf(v2 - m), e3 = __expf(v3 - m);
    float s = blockSum(e0 + e1 + e2 + e3, red, &stat, tid);
    float inv = 1.0f / s;
    p[tid] = e0 * inv; p[tid + 256] = e1 * inv; p[tid + 512] = e2 * inv; p[tid + 768] = e3 * inv;
}

// ---------------- attn @ V -> split bf16 ----------------
__global__ __launch_bounds__(256) void k_av(const float* __restrict__ sc,
                                            const float* __restrict__ qkv,
                                            __nv_bfloat16* __restrict__ oh,
                                            __nv_bfloat16* __restrict__ ol) {
    int bh = blockIdx.y;
    int b = bh / H_, h = bh % H_;
    int q0 = blockIdx.x << 6;
    int tid = threadIdx.x;
    int tr = tid >> 4, tc = tid & 15;

    __shared__ float Ps[64][65];
    __shared__ float Vs[64][65];

    float acc[4][4];
#pragma unroll
    for (int i = 0; i < 4; i++)
#pragma unroll
        for (int j = 0; j < 4; j++) acc[i][j] = 0.f;

    int nkt = blockIdx.x + 1;
    for (int kt = 0; kt < nkt; kt++) {
        for (int i = tid; i < 64 * 64; i += 256) {
            int r = i >> 6, c = i & 63;
            Ps[r][c] = sc[((size_t)bh * S_ + q0 + r) * S_ + kt * 64 + c];
            Vs[r][c] = qkv[(size_t)(b * S_ + kt * 64 + r) * E3_ + 2 * E_ + h * D_ + c];
        }
        __syncthreads();
#pragma unroll 4
        for (int k = 0; k < 64; k++) {
            float ra[4], rb[4];
#pragma unroll
            for (int i = 0; i < 4; i++) ra[i] = Ps[tr * 4 + i][k];
#pragma unroll
            for (int j = 0; j < 4; j++) rb[j] = Vs[k][tc * 4 + j];
#pragma unroll
            for (int i = 0; i < 4; i++)
#pragma unroll
                for (int j = 0; j < 4; j++) acc[i][j] = fmaf(ra[i], rb[j], acc[i][j]);
        }
        __syncthreads();
    }

#pragma unroll
    for (int i = 0; i < 4; i++) {
        int q = q0 + tr * 4 + i;
        size_t base = (size_t)(b * S_ + q) * E_ + h * D_ + tc * 4;
        BF4 hv, lv;
#pragma unroll
        for (int j = 0; j < 4; j++) {
            __nv_bfloat16 hh = __float2bfloat16(acc[i][j]);
            hv.b[j] = hh;
            lv.b[j] = __float2bfloat16(acc[i][j] - __bfloat162float(hh));
        }
        *(uint2*)&oh[base] = hv.u;
        *(uint2*)&ol[base] = lv.u;
    }
}

// ---------------- launcher ----------------
static inline void cvt(const float* src, __nv_bfloat16* h, __nv_bfloat16* l, int n) {
    int n4 = n / 4;
    k_cvt4<<<(n4 / 2 + 255) / 256, 256>>>((const float4*)src, (uint2*)h, (uint2*)l, n4);
}

extern "C" void kernel_launch(void* const* d_in, const int* in_sizes, int n_in,
                              void* d_out, int out_size) {
    (void)in_sizes; (void)n_in; (void)out_size;
    const int*   ids  = (const int*)  d_in[0];
    const float* wte  = (const float*)d_in[1];
    const float* wpe  = (const float*)d_in[2];
    const float* ln1s = (const float*)d_in[3];
    const float* ln1b = (const float*)d_in[4];
    const float* wqkv = (const float*)d_in[5];
    const float* bqkv = (const float*)d_in[6];
    const float* wao  = (const float*)d_in[7];
    const float* bao  = (const float*)d_in[8];
    const float* ln2s = (const float*)d_in[9];
    const float* ln2b = (const float*)d_in[10];
    const float* wfc  = (const float*)d_in[11];
    const float* bfc  = (const float*)d_in[12];
    const float* wmp  = (const float*)d_in[13];
    const float* bmp  = (const float*)d_in[14];
    const float* lnfs = (const float*)d_in[15];
    const float* lnfb = (const float*)d_in[16];
    const float* wlm  = (const float*)d_in[17];
    float* out = (float*)d_out;

    float *x, *qkv, *sc;
    cudaGetSymbolAddress((void**)&x,   g_x);
    cudaGetSymbolAddress((void**)&qkv, g_qkv);
    cudaGetSymbolAddress((void**)&sc,  g_scores);

    __nv_bfloat16 *wqh, *wql, *waoh, *waol, *wfh, *wfl, *wmh, *wml, *wlh, *wll;
    __nv_bfloat16 *aH, *aL, *bH, *bL;
    cudaGetSymbolAddress((void**)&wqh, g_wqkv_h);  cudaGetSymbolAddress((void**)&wql, g_wqkv_l);
    cudaGetSymbolAddress((void**)&waoh, g_wao_h);  cudaGetSymbolAddress((void**)&waol, g_wao_l);
    cudaGetSymbolAddress((void**)&wfh, g_wfc_h);   cudaGetSymbolAddress((void**)&wfl, g_wfc_l);
    cudaGetSymbolAddress((void**)&wmh, g_wmp_h);   cudaGetSymbolAddress((void**)&wml, g_wmp_l);
    cudaGetSymbolAddress((void**)&wlh, g_wlm_h);   cudaGetSymbolAddress((void**)&wll, g_wlm_l);
    cudaGetSymbolAddress((void**)&aH, g_a_h);      cudaGetSymbolAddress((void**)&aL, g_a_l);
    cudaGetSymbolAddress((void**)&bH, g_b_h);      cudaGetSymbolAddress((void**)&bL, g_b_l);

    // raise dynamic smem limits (idempotent)
    cudaFuncSetAttribute(k_gemm<true,  false, false, false>, cudaFuncAttributeMaxDynamicSharedMemorySize, GEMM_SMEM);
    cudaFuncSetAttribute(k_gemm<true,  false, true,  false>, cudaFuncAttributeMaxDynamicSharedMemorySize, GEMM_SMEM);
    cudaFuncSetAttribute(k_gemm<true,  true,  false, true >, cudaFuncAttributeMaxDynamicSharedMemorySize, GEMM_SMEM);
    cudaFuncSetAttribute(k_gemm<false, false, false, false>, cudaFuncAttributeMaxDynamicSharedMemorySize, GEMM_SMEM);

    // weight conversions (every call; deterministic)
    cvt(wqkv, wqh, wql, L_ * E_ * E3_);
    cvt(wao,  waoh, waol, L_ * E_ * E_);
    cvt(wfc,  wfh, wfl, L_ * E_ * E4_);
    cvt(wmp,  wmh, wml, L_ * E4_ * E_);
    k_cvt_pad<<<(E_ * VP_ / 4 / 2 + 255) / 256, 256>>>(wlm, (uint2*)wlh, (uint2*)wll);

    k_embed<<<M_, 256>>>(ids, wte, wpe, x);

    for (int l = 0; l < L_; l++) {
        // --- attention ---
        k_ln_split<<<M_, 256>>>(x, ln1s + l * E_, ln1b + l * E_, aH, aL);
        k_gemm<true, false, false, false><<<dim3(M_ / 128, E3_ / 128), 256, GEMM_SMEM>>>(
            aH, aL, wqh + (size_t)l * E_ * E3_, wql + (size_t)l * E_ * E3_,
            bqkv + l * E3_, nullptr, qkv, nullptr, nullptr, M_, E3_, E3_, E_);
        k_scores<<<dim3(S_ / 64, S_ / 64, BH_), 256>>>(qkv, sc);
        k_softmax<<<BH_ * S_, 256>>>(sc);
        k_av<<<dim3(S_ / 64, BH_), 256>>>(sc, qkv, aH, aL);
        k_gemm<true, false, true, false><<<dim3(M_ / 128, E_ / 128), 256, GEMM_SMEM>>>(
            aH, aL, waoh + (size_t)l * E_ * E_, waol + (size_t)l * E_ * E_,
            bao + l * E_, x, x, nullptr, nullptr, M_, E_, E_, E_);
        // --- MLP ---
        k_ln_split<<<M_, 256>>>(x, ln2s + l * E_, ln2b + l * E_, aH, aL);
        k_gemm<true, true, false, true><<<dim3(M_ / 128, E4_ / 128), 256, GEMM_SMEM>>>(
            aH, aL, wfh + (size_t)l * E_ * E4_, wfl + (size_t)l * E_ * E4_,
            bfc + l * E4_, nullptr, nullptr, bH, bL, M_, E4_, E4_, E_);
        k_gemm<true, false, true, false><<<dim3(M_ / 128, E_ / 128), 256, GEMM_SMEM>>>(
            bH, bL, wmh + (size_t)l * E4_ * E_, wml + (size_t)l * E4_ * E_,
            bmp + l * E_, x, x, nullptr, nullptr, M_, E_, E_, E4_);
    }

    // --- final LN + LM head ---
    k_ln_split<<<M_, 256>>>(x, lnfs, lnfb, aH, aL);
    k_gemm<false, false, false, false><<<dim3(M_ / 128, VP_ / 128), 256, GEMM_SMEM>>>(
        aH, aL, wlh, wll, nullptr, nullptr, out, nullptr, nullptr, M_, V_, VP_, E_);
}